// round 15
// baseline (speedup 1.0000x reference)
#include <cuda_runtime.h>
#include <cuda_fp16.h>
#include <cstdint>
#include <cstddef>

#define DINLINE __device__ __forceinline__

static constexpr int BATCH = 4096;
static constexpr int ROWS  = BATCH * 2;   // 8192 GEMM rows
static constexpr int FEAT  = 41024;       // K
static constexpr int MOUT  = 512;         // N

// CTA tile 128x128, 256 threads, warp grid 4(M) x 2(N), warp tile 32x64
static constexpr int TILE_M = 128;
static constexpr int TILE_N = 128;
static constexpr int KC     = 64;               // fp16 K per stage (128B rows)
static constexpr int NSTAGE = FEAT / KC;        // 641 exact

static constexpr unsigned OFF_A = 0u;           // A tile 128x64 fp16 = 16KB
static constexpr unsigned OFF_B = 16384u;       // B tile 128x64 fp16 = 16KB
static constexpr unsigned BUF_STRIDE = 32768u;  // 32KB per stage
static constexpr int NBUF = 3;
static constexpr unsigned DYN_SMEM = 1024u + (unsigned)NBUF * BUF_STRIDE; // 99328

// producer/consumer split: one wave = 296 CTAs @ 2 per SM
static constexpr int NPROD  = 40;               // producer CTAs (fp32->fp16 convert)
static constexpr int NGEMM  = 256;              // consumer CTAs (64 M-tiles x 4 N-tiles)
static constexpr int NCHUNK = 16;               // K-chunks; 15 x 40 stages + 1 x 41
static constexpr int CH_ST  = 40;               // stages per chunk (except last)

static constexpr size_t NFEL = (size_t)ROWS * FEAT;
static constexpr size_t NWEL = (size_t)MOUT * FEAT;
static constexpr size_t NW4  = NWEL / 4;

__device__ __align__(256) __half g_feat_h[NFEL];              // 672 MB
__device__ __align__(256) __half g_w_h[NWEL];                 // 42 MB
__device__ __align__(256) float  g_acc[(size_t)ROWS * MOUT];  // 16 MB
__device__ __align__(256) float  g_corr[MOUT];                // w_lo mean correction
__device__ int g_cnt[NCHUNK];
__device__ int g_flag[NCHUNK];

// ---------------- PTX helpers (base ISA, sm_80+) ----------------
DINLINE uint32_t smem_u32(const void* p) {
    uint32_t a;
    asm("{ .reg .u64 t; cvta.to.shared.u64 t, %1; cvt.u32.u64 %0, t; }" : "=r"(a) : "l"(p));
    return a;
}
DINLINE void cp_async16(uint32_t dst, const void* src) {
    asm volatile("cp.async.cg.shared.global [%0], [%1], 16;" :: "r"(dst), "l"(src) : "memory");
}
DINLINE void cp_commit() { asm volatile("cp.async.commit_group;" ::: "memory"); }
template <int N> DINLINE void cp_wait() { asm volatile("cp.async.wait_group %0;" :: "n"(N) : "memory"); }

DINLINE void ldsm_x4(uint32_t& r0, uint32_t& r1, uint32_t& r2, uint32_t& r3, uint32_t a) {
    asm volatile("ldmatrix.sync.aligned.m8n8.x4.shared.b16 {%0,%1,%2,%3}, [%4];"
                 : "=r"(r0), "=r"(r1), "=r"(r2), "=r"(r3) : "r"(a));
}
DINLINE void mma16816(float* c, const uint32_t* a, const uint32_t* b) {
    asm volatile(
        "mma.sync.aligned.m16n8k16.row.col.f32.f16.f16.f32 "
        "{%0,%1,%2,%3}, {%4,%5,%6,%7}, {%8,%9}, {%0,%1,%2,%3};"
        : "+f"(c[0]), "+f"(c[1]), "+f"(c[2]), "+f"(c[3])
        : "r"(a[0]), "r"(a[1]), "r"(a[2]), "r"(a[3]), "r"(b[0]), "r"(b[1]));
}
DINLINE int ld_acquire(const int* p) {
    int v;
    asm volatile("ld.acquire.gpu.global.b32 %0, [%1];" : "=r"(v) : "l"(p) : "memory");
    return v;
}

// ---------------- kernel 1: W_ft fp32 -> fp16, plus flag reset ----------------
__global__ void k_convert_w(const float* __restrict__ src) {
    size_t i = (size_t)blockIdx.x * blockDim.x + threadIdx.x;
    if (blockIdx.x == 0 && threadIdx.x < 2 * NCHUNK) {   // reset producer flags each call
        if (threadIdx.x < NCHUNK) g_cnt[threadIdx.x] = 0;
        else g_flag[threadIdx.x - NCHUNK] = 0;
    }
    if (i >= NW4) return;
    float4 v = reinterpret_cast<const float4*>(src)[i];
    __half2* dst = reinterpret_cast<__half2*>(g_w_h);
    dst[2 * i + 0] = __floats2half2_rn(v.x, v.y);
    dst[2 * i + 1] = __floats2half2_rn(v.z, v.w);
}

// ---------------- kernel 1c: per-neuron mean correction for dropped w_lo ----------------
// corr[m] = E[f] * sum_k (w - fp16(w)) = 0.5 * sum_k w_lo[m,k]
__global__ __launch_bounds__(256) void k_wcorr(const float* __restrict__ W) {
    __shared__ float red[8];
    const int m = blockIdx.x, t = threadIdx.x;
    const float* row = W + (size_t)m * FEAT;
    float s = 0.f;
    for (int k = t; k < FEAT; k += 256) {
        float w = row[k];
        s += w - __half2float(__float2half_rn(w));
    }
#pragma unroll
    for (int o = 16; o; o >>= 1) s += __shfl_xor_sync(0xffffffffu, s, o);
    if ((t & 31) == 0) red[t >> 5] = s;
    __syncthreads();
    if (t < 8) {
        s = red[t];
#pragma unroll
        for (int o = 4; o; o >>= 1) s += __shfl_xor_sync(0xffu, s, o);
        if (t == 0) g_corr[m] = 0.5f * s;
    }
}

// ---------------- producer: convert features fp32->fp16 by K-chunk, publish flags ----
DINLINE void producer_body(const float* __restrict__ src, int pid, int tid) {
#pragma unroll 1
    for (int c = 0; c < NCHUNK; ++c) {
        const int s0 = c * CH_ST;
        const int ns = (c == NCHUNK - 1) ? (NSTAGE - CH_ST * (NCHUNK - 1)) : CH_ST;
        const int f4_per_row = ns * 16;                 // float4 per row in this chunk
        const size_t nf4 = (size_t)ROWS * f4_per_row;
#pragma unroll 1
        for (size_t i = (size_t)pid * 256 + tid; i < nf4; i += (size_t)NPROD * 256) {
            const size_t r = i / (size_t)f4_per_row;
            const int rem = (int)(i - r * f4_per_row);
            const int s = s0 + (rem >> 4), q = rem & 15;
            const size_t off = r * FEAT + (size_t)s * KC + (size_t)q * 4;
            float4 v = *reinterpret_cast<const float4*>(src + off);
            __half2 h0 = __floats2half2_rn(v.x, v.y);
            __half2 h1 = __floats2half2_rn(v.z, v.w);
            uint2 u = make_uint2(*reinterpret_cast<uint32_t*>(&h0),
                                 *reinterpret_cast<uint32_t*>(&h1));
            *reinterpret_cast<uint2*>(g_feat_h + off) = u;
        }
        __syncthreads();
        __threadfence();
        if (tid == 0) {
            int v = atomicAdd(&g_cnt[c], 1);
            if (v == NPROD - 1) atomicExch(&g_flag[c], 1);
        }
    }
}

// ---------------- kernel 2: fused producer + mma.sync fp16 GEMM ----------------
__global__ __launch_bounds__(256, 2) void k_fused(const float* __restrict__ feat) {
    const int tid = threadIdx.x;
    if (blockIdx.x < NPROD) { producer_body(feat, blockIdx.x, tid); return; }

    extern __shared__ char smem_raw[];
    const uint32_t sraw = smem_u32(smem_raw);
    const uint32_t bufs = (sraw + 1023u) & ~1023u;

    const int gb = blockIdx.x - NPROD;   // 0..255
    const int nb = gb & 3;               // fastest -> A-slab L2 dedup
    const int rb = gb >> 2;              // 0..63
    const int lane = tid & 31, wid = tid >> 5;
    const int warp_m = wid >> 1, warp_n = wid & 1;   // 4 x 2

    const __half* Ag = g_feat_h + (size_t)(rb * TILE_M) * FEAT;
    const __half* Bg = g_w_h + (size_t)(nb * TILE_N) * FEAT;

    // 16B-chunk loader, 128B smem rows, XOR swizzle ((row&7)<<4)
    auto load_stage = [&](int s, int buf) {
        const uint32_t bb = bufs + (unsigned)buf * BUF_STRIDE;
        const int k0 = s * KC;
#pragma unroll
        for (int it = 0; it < 4; ++it) {            // A: 1024 chunks
            int c = tid + it * 256;
            int row = c >> 3, c16 = c & 7;
            uint32_t d = bb + OFF_A + (unsigned)(row * 128 + ((c16 * 16) ^ ((row & 7) << 4)));
            cp_async16(d, Ag + (size_t)row * FEAT + k0 + c16 * 8);
        }
#pragma unroll
        for (int it = 0; it < 4; ++it) {            // B: 1024 chunks
            int c = tid + it * 256;
            int row = c >> 3, c16 = c & 7;
            uint32_t d = bb + OFF_B + (unsigned)(row * 128 + ((c16 * 16) ^ ((row & 7) << 4)));
            cp_async16(d, Bg + (size_t)row * FEAT + k0 + c16 * 8);
        }
        cp_commit();
    };

    int ready = -1;
    auto wait_chunk = [&](int s) {
        int c = s / CH_ST; if (c > NCHUNK - 1) c = NCHUNK - 1;
        if (c > ready) {
            if (tid == 0)
                while (ld_acquire(&g_flag[c]) == 0) __nanosleep(200);
            __syncthreads();
            ready = c;
        }
    };

    // ldmatrix per-lane geometry (validated R11-R13)
    const int rowA = lane & 15;
    const int khA  = lane >> 4;
    const int rowB = (lane & 7) + 8 * (lane >> 4);
    const int khB  = (lane >> 3) & 1;
    const uint32_t swz = (uint32_t)((lane & 7) << 4);

    float acc[2][8][4];
#pragma unroll
    for (int i = 0; i < 2; ++i)
#pragma unroll
        for (int j = 0; j < 8; ++j)
#pragma unroll
            for (int q = 0; q < 4; ++q) acc[i][j][q] = 0.f;

    wait_chunk(1);            // stages 0 and 1 are both inside chunk 0
    load_stage(0, 0);
    load_stage(1, 1);

#pragma unroll 1
    for (int s = 0; s < NSTAGE; ++s) {
        if (s < NSTAGE - 1) cp_wait<1>(); else cp_wait<0>();
        __syncthreads();  // stage s visible; all warps done with stage s-1

        if (s + 2 < NSTAGE) {
            wait_chunk(s + 2);
            load_stage(s + 2, (s + 2) % NBUF);  // buf (s-1)%3 is free
        }

        const uint32_t bb = bufs + (unsigned)(s % NBUF) * BUF_STRIDE;
        const uint32_t baseA = bb + OFF_A + (unsigned)((warp_m * 32 + rowA) * 128);
        const uint32_t baseB = bb + OFF_B + (unsigned)((warp_n * 64 + rowB) * 128);

#pragma unroll
        for (int ks = 0; ks < 4; ++ks) {
            const uint32_t CA = (uint32_t)((ks * 32) | (khA * 16)) ^ swz;
            const uint32_t CB = (uint32_t)((ks * 32) | (khB * 16)) ^ swz;
            uint32_t a[2][4], b[4][4];
#pragma unroll
            for (int i = 0; i < 2; ++i)
                ldsm_x4(a[i][0], a[i][1], a[i][2], a[i][3],
                        baseA + (unsigned)(i * 16 * 128) + CA);
#pragma unroll
            for (int j2 = 0; j2 < 4; ++j2)
                ldsm_x4(b[j2][0], b[j2][1], b[j2][2], b[j2][3],
                        baseB + (unsigned)(j2 * 16 * 128) + CB);
#pragma unroll
            for (int i = 0; i < 2; ++i)
#pragma unroll
                for (int j2 = 0; j2 < 4; ++j2) {
                    mma16816(acc[i][2 * j2 + 0], a[i], &b[j2][0]);
                    mma16816(acc[i][2 * j2 + 1], a[i], &b[j2][2]);
                }
        }
    }

    // epilogue: fragments -> g_acc (fp32)
    const int r  = lane >> 2;
    const int cc = 2 * (lane & 3);
    const int m0 = rb * TILE_M + warp_m * 32;
    const int n0 = nb * TILE_N + warp_n * 64;
#pragma unroll
    for (int i = 0; i < 2; ++i)
#pragma unroll
        for (int j = 0; j < 8; ++j) {
            const int m = m0 + i * 16 + r;
            const int n = n0 + j * 8 + cc;
            *reinterpret_cast<float2*>(&g_acc[(size_t)m * MOUT + n]) =
                make_float2(acc[i][j][0], acc[i][j][1]);
            *reinterpret_cast<float2*>(&g_acc[(size_t)(m + 8) * MOUT + n]) =
                make_float2(acc[i][j][2], acc[i][j][3]);
        }
}

// ---------------- kernel 3: bias + corr + stm + clip + MLP head ----------------
__global__ __launch_bounds__(128) void k_mlp(const float* __restrict__ stm,
                                             const float* __restrict__ b_ft,
                                             const float* __restrict__ W1,
                                             const float* __restrict__ b1,
                                             const float* __restrict__ W2,
                                             const float* __restrict__ b2,
                                             float* __restrict__ out) {
    __shared__ float l1[1024];
    __shared__ float l2[32];
    const int b = blockIdx.x, t = threadIdx.x;
    const float s0 = stm[b * 2 + 0], s1 = stm[b * 2 + 1];
#pragma unroll
    for (int it = 0; it < 8; ++it) {
        int i = t + it * 128;
        int p = i >> 9, m = i & 511;
        float v = (g_acc[(size_t)(b * 2 + p) * MOUT + m] + g_corr[m] + b_ft[m]) * (p ? s1 : s0);
        l1[i] = fminf(fmaxf(v, 0.f), 1.f);
    }
    __syncthreads();
    const int w = t >> 5, lane = t & 31;
#pragma unroll 1
    for (int jj = 0; jj < 8; ++jj) {
        int j = w * 8 + jj;
        const float* wr = W1 + (size_t)j * 1024;
        float s = 0.f;
#pragma unroll 8
        for (int i = lane; i < 1024; i += 32) s += l1[i] * wr[i];
#pragma unroll
        for (int o = 16; o; o >>= 1) s += __shfl_xor_sync(0xffffffffu, s, o);
        if (lane == 0) l2[j] = fminf(fmaxf(s + b1[j], 0.f), 1.f);
    }
    __syncthreads();
    if (t < 32) {
        float s = l2[t] * W2[t];
#pragma unroll
        for (int o = 16; o; o >>= 1) s += __shfl_xor_sync(0xffffffffu, s, o);
        if (t == 0) out[b] = s + b2[0];
    }
}

extern "C" void kernel_launch(void* const* d_in, const int* in_sizes, int n_in,
                              void* d_out, int out_size) {
    const float* features = (const float*)d_in[0];
    const float* stm      = (const float*)d_in[1];
    const float* W_ft     = (const float*)d_in[2];
    const float* b_ft     = (const float*)d_in[3];
    const float* W1       = (const float*)d_in[4];
    const float* b1       = (const float*)d_in[5];
    const float* W2       = (const float*)d_in[6];
    const float* b2       = (const float*)d_in[7];
    float* out = (float*)d_out;

    cudaFuncSetAttribute(k_fused, cudaFuncAttributeMaxDynamicSharedMemorySize, DYN_SMEM);

    k_convert_w<<<(unsigned)((NW4 + 255) / 256), 256>>>(W_ft);   // also resets flags
    k_fused<<<NPROD + NGEMM, 256, DYN_SMEM>>>(features);
    k_wcorr<<<MOUT, 256>>>(W_ft);
    k_mlp<<<BATCH, 128>>>(stm, b_ft, W1, b1, W2, b2, out);
}

// round 16
// speedup vs baseline: 4.2337x; 4.2337x over previous
#include <cuda_runtime.h>
#include <cuda_fp16.h>
#include <cstdint>
#include <cstddef>

#define DINLINE __device__ __forceinline__

static constexpr int BATCH = 4096;
static constexpr int ROWS  = BATCH * 2;   // 8192 GEMM rows
static constexpr int FEAT  = 41024;       // K
static constexpr int MOUT  = 512;         // N

// CTA tile 128x128, 128 threads, warp grid 2(M) x 2(N), warp tile 64x64
static constexpr int TILE_M = 128;
static constexpr int TILE_N = 128;
static constexpr int KC     = 64;               // fp16 K per stage (128B rows)
static constexpr int NSTAGE = FEAT / KC;        // 641 exact

static constexpr unsigned OFF_A = 0u;           // A tile 128x64 fp16 = 16KB
static constexpr unsigned OFF_B = 16384u;       // B tile 128x64 fp16 = 16KB
static constexpr unsigned BUF_STRIDE = 32768u;  // 32KB per stage
static constexpr int NBUF = 3;
static constexpr unsigned DYN_SMEM = 1024u + (unsigned)NBUF * BUF_STRIDE; // 99328

static constexpr size_t NFEL = (size_t)ROWS * FEAT;
static constexpr size_t NWEL = (size_t)MOUT * FEAT;
static constexpr size_t NF8  = NFEL / 8;
static constexpr size_t NW4  = NWEL / 4;

__device__ __align__(256) __half g_feat_h[NFEL];              // 672 MB
__device__ __align__(256) __half g_w_h[NWEL];                 // 42 MB
__device__ __align__(256) float  g_acc[(size_t)ROWS * MOUT];  // 16 MB
__device__ __align__(256) float  g_corr[MOUT];                // w_lo mean correction

// ---------------- PTX helpers (base ISA, sm_80+) ----------------
DINLINE uint32_t smem_u32(const void* p) {
    uint32_t a;
    asm("{ .reg .u64 t; cvta.to.shared.u64 t, %1; cvt.u32.u64 %0, t; }" : "=r"(a) : "l"(p));
    return a;
}
DINLINE void cp_async16(uint32_t dst, const void* src) {
    asm volatile("cp.async.cg.shared.global [%0], [%1], 16;" :: "r"(dst), "l"(src) : "memory");
}
DINLINE void cp_commit() { asm volatile("cp.async.commit_group;" ::: "memory"); }
template <int N> DINLINE void cp_wait() { asm volatile("cp.async.wait_group %0;" :: "n"(N) : "memory"); }

DINLINE void ldsm_x4(uint32_t& r0, uint32_t& r1, uint32_t& r2, uint32_t& r3, uint32_t a) {
    asm volatile("ldmatrix.sync.aligned.m8n8.x4.shared.b16 {%0,%1,%2,%3}, [%4];"
                 : "=r"(r0), "=r"(r1), "=r"(r2), "=r"(r3) : "r"(a));
}
DINLINE void mma16816(float* c, const uint32_t* a, const uint32_t* b) {
    asm volatile(
        "mma.sync.aligned.m16n8k16.row.col.f32.f16.f16.f32 "
        "{%0,%1,%2,%3}, {%4,%5,%6,%7}, {%8,%9}, {%0,%1,%2,%3};"
        : "+f"(c[0]), "+f"(c[1]), "+f"(c[2]), "+f"(c[3])
        : "r"(a[0]), "r"(a[1]), "r"(a[2]), "r"(a[3]), "r"(b[0]), "r"(b[1]));
}

// ---------------- kernel 1a: features fp32 -> fp16 (8 floats/thread, 16B stores) ------
__global__ void k_convert_feat(const float* __restrict__ src) {
    size_t i = (size_t)blockIdx.x * blockDim.x + threadIdx.x;
    if (i >= NF8) return;
    const float4* s4 = reinterpret_cast<const float4*>(src) + 2 * i;
    float4 v0 = s4[0], v1 = s4[1];
    __half2 h0 = __floats2half2_rn(v0.x, v0.y);
    __half2 h1 = __floats2half2_rn(v0.z, v0.w);
    __half2 h2 = __floats2half2_rn(v1.x, v1.y);
    __half2 h3 = __floats2half2_rn(v1.z, v1.w);
    uint4 u = make_uint4(*reinterpret_cast<uint32_t*>(&h0), *reinterpret_cast<uint32_t*>(&h1),
                         *reinterpret_cast<uint32_t*>(&h2), *reinterpret_cast<uint32_t*>(&h3));
    reinterpret_cast<uint4*>(g_feat_h)[i] = u;
}

// ---------------- kernel 1b: W_ft fp32 -> fp16 ----------------
__global__ void k_convert_w(const float* __restrict__ src) {
    size_t i = (size_t)blockIdx.x * blockDim.x + threadIdx.x;
    if (i >= NW4) return;
    float4 v = reinterpret_cast<const float4*>(src)[i];
    __half2* dst = reinterpret_cast<__half2*>(g_w_h);
    dst[2 * i + 0] = __floats2half2_rn(v.x, v.y);
    dst[2 * i + 1] = __floats2half2_rn(v.z, v.w);
}

// ---------------- kernel 1c: per-neuron mean correction for dropped w_lo ----------------
// corr[m] = E[f] * sum_k (w - fp16(w)) = 0.5 * sum_k w_lo[m,k]
__global__ __launch_bounds__(256) void k_wcorr(const float* __restrict__ W) {
    __shared__ float red[8];
    const int m = blockIdx.x, t = threadIdx.x;
    const float* row = W + (size_t)m * FEAT;
    float s = 0.f;
    for (int k = t; k < FEAT; k += 256) {
        float w = row[k];
        s += w - __half2float(__float2half_rn(w));
    }
#pragma unroll
    for (int o = 16; o; o >>= 1) s += __shfl_xor_sync(0xffffffffu, s, o);
    if ((t & 31) == 0) red[t >> 5] = s;
    __syncthreads();
    if (t < 8) {
        s = red[t];
#pragma unroll
        for (int o = 4; o; o >>= 1) s += __shfl_xor_sync(0xffu, s, o);
        if (t == 0) g_corr[m] = 0.5f * s;
    }
}

// ---------------- kernel 2: mma.sync fp16 GEMM, 4 warps, warp tile 64x64, 2 CTAs/SM ----
__global__ __launch_bounds__(128, 2) void k_gemm() {
    extern __shared__ char smem_raw[];
    const uint32_t sraw = smem_u32(smem_raw);
    const uint32_t bufs = (sraw + 1023u) & ~1023u;

    const int tid = threadIdx.x;
    const int lane = tid & 31, wid = tid >> 5;
    const int warp_m = wid >> 1, warp_n = wid & 1;   // 2 x 2
    const int nb = blockIdx.x;   // 0..3  (N tiles)  fastest -> A-slab L2 dedup
    const int rb = blockIdx.y;   // 0..63 (M tiles)

    const __half* Ag = g_feat_h + (size_t)(rb * TILE_M) * FEAT;
    const __half* Bg = g_w_h + (size_t)(nb * TILE_N) * FEAT;

    // 16B-chunk loader, 128B smem rows, XOR swizzle ((row&7)<<4); 128 threads
    auto load_stage = [&](int s, int buf) {
        const uint32_t bb = bufs + (unsigned)buf * BUF_STRIDE;
        const int k0 = s * KC;
#pragma unroll
        for (int it = 0; it < 8; ++it) {            // A: 1024 chunks
            int c = tid + it * 128;
            int row = c >> 3, c16 = c & 7;
            uint32_t d = bb + OFF_A + (unsigned)(row * 128 + ((c16 * 16) ^ ((row & 7) << 4)));
            cp_async16(d, Ag + (size_t)row * FEAT + k0 + c16 * 8);
        }
#pragma unroll
        for (int it = 0; it < 8; ++it) {            // B: 1024 chunks
            int c = tid + it * 128;
            int row = c >> 3, c16 = c & 7;
            uint32_t d = bb + OFF_B + (unsigned)(row * 128 + ((c16 * 16) ^ ((row & 7) << 4)));
            cp_async16(d, Bg + (size_t)row * FEAT + k0 + c16 * 8);
        }
        cp_commit();
    };

    // ldmatrix per-lane geometry (validated R11-R13)
    const int rowA = lane & 15;
    const int khA  = lane >> 4;
    const int rowB = (lane & 7) + 8 * (lane >> 4);
    const int khB  = (lane >> 3) & 1;
    const uint32_t swz = (uint32_t)((lane & 7) << 4);

    float acc[4][8][4];
#pragma unroll
    for (int i = 0; i < 4; ++i)
#pragma unroll
        for (int j = 0; j < 8; ++j)
#pragma unroll
            for (int q = 0; q < 4; ++q) acc[i][j][q] = 0.f;

    load_stage(0, 0);
    load_stage(1, 1);

#pragma unroll 1
    for (int s = 0; s < NSTAGE; ++s) {
        if (s < NSTAGE - 1) cp_wait<1>(); else cp_wait<0>();
        __syncthreads();  // stage s visible; all warps done with stage s-1

        if (s + 2 < NSTAGE) load_stage(s + 2, (s + 2) % NBUF);  // buf (s-1)%3 is free

        const uint32_t bb = bufs + (unsigned)(s % NBUF) * BUF_STRIDE;
        const uint32_t baseA = bb + OFF_A + (unsigned)((warp_m * 64 + rowA) * 128);
        const uint32_t baseB = bb + OFF_B + (unsigned)((warp_n * 64 + rowB) * 128);

#pragma unroll
        for (int ks = 0; ks < 4; ++ks) {
            const uint32_t CA = (uint32_t)((ks * 32) | (khA * 16)) ^ swz;
            const uint32_t CB = (uint32_t)((ks * 32) | (khB * 16)) ^ swz;
            uint32_t a[4][4], b[4][4];
#pragma unroll
            for (int i = 0; i < 4; ++i)
                ldsm_x4(a[i][0], a[i][1], a[i][2], a[i][3],
                        baseA + (unsigned)(i * 16 * 128) + CA);
#pragma unroll
            for (int j2 = 0; j2 < 4; ++j2)
                ldsm_x4(b[j2][0], b[j2][1], b[j2][2], b[j2][3],
                        baseB + (unsigned)(j2 * 16 * 128) + CB);
#pragma unroll
            for (int i = 0; i < 4; ++i)
#pragma unroll
                for (int j2 = 0; j2 < 4; ++j2) {
                    mma16816(acc[i][2 * j2 + 0], a[i], &b[j2][0]);
                    mma16816(acc[i][2 * j2 + 1], a[i], &b[j2][2]);
                }
        }
    }

    // epilogue: fragments -> g_acc (fp32)
    const int r  = lane >> 2;
    const int cc = 2 * (lane & 3);
    const int m0 = rb * TILE_M + warp_m * 64;
    const int n0 = nb * TILE_N + warp_n * 64;
#pragma unroll
    for (int i = 0; i < 4; ++i)
#pragma unroll
        for (int j = 0; j < 8; ++j) {
            const int m = m0 + i * 16 + r;
            const int n = n0 + j * 8 + cc;
            *reinterpret_cast<float2*>(&g_acc[(size_t)m * MOUT + n]) =
                make_float2(acc[i][j][0], acc[i][j][1]);
            *reinterpret_cast<float2*>(&g_acc[(size_t)(m + 8) * MOUT + n]) =
                make_float2(acc[i][j][2], acc[i][j][3]);
        }
}

// ---------------- kernel 3: bias + corr + stm + clip + MLP head ----------------
__global__ __launch_bounds__(128) void k_mlp(const float* __restrict__ stm,
                                             const float* __restrict__ b_ft,
                                             const float* __restrict__ W1,
                                             const float* __restrict__ b1,
                                             const float* __restrict__ W2,
                                             const float* __restrict__ b2,
                                             float* __restrict__ out) {
    __shared__ float l1[1024];
    __shared__ float l2[32];
    const int b = blockIdx.x, t = threadIdx.x;
    const float s0 = stm[b * 2 + 0], s1 = stm[b * 2 + 1];
#pragma unroll
    for (int it = 0; it < 8; ++it) {
        int i = t + it * 128;
        int p = i >> 9, m = i & 511;
        float v = (g_acc[(size_t)(b * 2 + p) * MOUT + m] + g_corr[m] + b_ft[m]) * (p ? s1 : s0);
        l1[i] = fminf(fmaxf(v, 0.f), 1.f);
    }
    __syncthreads();
    const int w = t >> 5, lane = t & 31;
#pragma unroll 1
    for (int jj = 0; jj < 8; ++jj) {
        int j = w * 8 + jj;
        const float* wr = W1 + (size_t)j * 1024;
        float s = 0.f;
#pragma unroll 8
        for (int i = lane; i < 1024; i += 32) s += l1[i] * wr[i];
#pragma unroll
        for (int o = 16; o; o >>= 1) s += __shfl_xor_sync(0xffffffffu, s, o);
        if (lane == 0) l2[j] = fminf(fmaxf(s + b1[j], 0.f), 1.f);
    }
    __syncthreads();
    if (t < 32) {
        float s = l2[t] * W2[t];
#pragma unroll
        for (int o = 16; o; o >>= 1) s += __shfl_xor_sync(0xffffffffu, s, o);
        if (t == 0) out[b] = s + b2[0];
    }
}

extern "C" void kernel_launch(void* const* d_in, const int* in_sizes, int n_in,
                              void* d_out, int out_size) {
    const float* features = (const float*)d_in[0];
    const float* stm      = (const float*)d_in[1];
    const float* W_ft     = (const float*)d_in[2];
    const float* b_ft     = (const float*)d_in[3];
    const float* W1       = (const float*)d_in[4];
    const float* b1       = (const float*)d_in[5];
    const float* W2       = (const float*)d_in[6];
    const float* b2       = (const float*)d_in[7];
    float* out = (float*)d_out;

    cudaFuncSetAttribute(k_gemm, cudaFuncAttributeMaxDynamicSharedMemorySize, DYN_SMEM);

    k_convert_feat<<<(unsigned)((NF8 + 255) / 256), 256>>>(features);
    k_convert_w<<<(unsigned)((NW4 + 255) / 256), 256>>>(W_ft);
    k_wcorr<<<MOUT, 256>>>(W_ft);
    k_gemm<<<dim3(4, 64), 128, DYN_SMEM>>>();
    k_mlp<<<BATCH, 128>>>(stm, b_ft, W1, b1, W2, b2, out);
}

// round 17
// speedup vs baseline: 4.9186x; 1.1618x over previous
#include <cuda_runtime.h>
#include <cuda_fp16.h>
#include <cstdint>
#include <cstddef>

#define DINLINE __device__ __forceinline__

static constexpr int BATCH = 4096;
static constexpr int ROWS  = BATCH * 2;   // 8192 GEMM rows
static constexpr int FEAT  = 41024;       // K
static constexpr int MOUT  = 512;         // N

// CTA tile 128x128, 128 threads, warp grid 2(M) x 2(N), warp tile 64x64
static constexpr int TILE_M = 128;
static constexpr int TILE_N = 128;
static constexpr int KC     = 64;               // fp16 K per stage (128B rows)
static constexpr int NSTAGE = FEAT / KC;        // 641 exact

static constexpr unsigned OFF_A = 0u;           // A tile 128x64 fp16 = 16KB
static constexpr unsigned OFF_B = 16384u;       // B tile 128x64 fp16 = 16KB
static constexpr unsigned BUF_STRIDE = 32768u;  // 32KB per stage
static constexpr unsigned DYN_SMEM = 1024u + 3u * BUF_STRIDE; // 99328

static constexpr size_t NFEL = (size_t)ROWS * FEAT;
static constexpr size_t NWEL = (size_t)MOUT * FEAT;
static constexpr size_t NF8  = NFEL / 8;

__device__ __align__(256) __half g_feat_h[NFEL];              // 672 MB
__device__ __align__(256) __half g_w_h[NWEL];                 // 42 MB
__device__ __align__(256) float  g_acc[(size_t)ROWS * MOUT];  // 16 MB
__device__ __align__(256) float  g_corr[MOUT];                // w_lo mean correction

// ---------------- PTX helpers (base ISA, sm_80+) ----------------
DINLINE uint32_t smem_u32(const void* p) {
    uint32_t a;
    asm("{ .reg .u64 t; cvta.to.shared.u64 t, %1; cvt.u32.u64 %0, t; }" : "=r"(a) : "l"(p));
    return a;
}
DINLINE void cp_async16(uint32_t dst, const void* src) {
    asm volatile("cp.async.cg.shared.global [%0], [%1], 16;" :: "r"(dst), "l"(src) : "memory");
}
DINLINE void cp_commit() { asm volatile("cp.async.commit_group;" ::: "memory"); }
template <int N> DINLINE void cp_wait() { asm volatile("cp.async.wait_group %0;" :: "n"(N) : "memory"); }

DINLINE void ldsm_x4(uint32_t& r0, uint32_t& r1, uint32_t& r2, uint32_t& r3, uint32_t a) {
    asm volatile("ldmatrix.sync.aligned.m8n8.x4.shared.b16 {%0,%1,%2,%3}, [%4];"
                 : "=r"(r0), "=r"(r1), "=r"(r2), "=r"(r3) : "r"(a));
}
DINLINE void mma16816(float* c, const uint32_t* a, const uint32_t* b) {
    asm volatile(
        "mma.sync.aligned.m16n8k16.row.col.f32.f16.f16.f32 "
        "{%0,%1,%2,%3}, {%4,%5,%6,%7}, {%8,%9}, {%0,%1,%2,%3};"
        : "+f"(c[0]), "+f"(c[1]), "+f"(c[2]), "+f"(c[3])
        : "r"(a[0]), "r"(a[1]), "r"(a[2]), "r"(a[3]), "r"(b[0]), "r"(b[1]));
}

// ---------------- kernel 1a: features fp32 -> fp16 (8 floats/thread) ----------------
__global__ void k_convert_feat(const float* __restrict__ src) {
    size_t i = (size_t)blockIdx.x * blockDim.x + threadIdx.x;
    if (i >= NF8) return;
    const float4* s4 = reinterpret_cast<const float4*>(src) + 2 * i;
    float4 v0 = s4[0], v1 = s4[1];
    __half2 h0 = __floats2half2_rn(v0.x, v0.y);
    __half2 h1 = __floats2half2_rn(v0.z, v0.w);
    __half2 h2 = __floats2half2_rn(v1.x, v1.y);
    __half2 h3 = __floats2half2_rn(v1.z, v1.w);
    uint4 u = make_uint4(*reinterpret_cast<uint32_t*>(&h0), *reinterpret_cast<uint32_t*>(&h1),
                         *reinterpret_cast<uint32_t*>(&h2), *reinterpret_cast<uint32_t*>(&h3));
    reinterpret_cast<uint4*>(g_feat_h)[i] = u;
}

// ---------------- kernel 1b: W_ft fp32 -> fp16 AND mean correction, one pass -------
// corr[m] = 0.5 * sum_k (w - fp16(w))
__global__ __launch_bounds__(256) void k_convert_wc(const float* __restrict__ W) {
    __shared__ float red[8];
    const int m = blockIdx.x, t = threadIdx.x;
    const float* row = W + (size_t)m * FEAT;
    __half2* drow = reinterpret_cast<__half2*>(g_w_h + (size_t)m * FEAT);
    float s = 0.f;
    for (int i4 = t; i4 < FEAT / 4; i4 += 256) {
        float4 v = reinterpret_cast<const float4*>(row)[i4];
        __half2 h0 = __floats2half2_rn(v.x, v.y);
        __half2 h1 = __floats2half2_rn(v.z, v.w);
        drow[2 * i4 + 0] = h0;
        drow[2 * i4 + 1] = h1;
        s += (v.x - __low2float(h0)) + (v.y - __high2float(h0))
           + (v.z - __low2float(h1)) + (v.w - __high2float(h1));
    }
#pragma unroll
    for (int o = 16; o; o >>= 1) s += __shfl_xor_sync(0xffffffffu, s, o);
    if ((t & 31) == 0) red[t >> 5] = s;
    __syncthreads();
    if (t < 8) {
        s = red[t];
#pragma unroll
        for (int o = 4; o; o >>= 1) s += __shfl_xor_sync(0xffu, s, o);
        if (t == 0) g_corr[m] = 0.5f * s;
    }
}

// ---------------- kernel 2: mma.sync fp16 GEMM, lean loader + A-frag pipelining ------
__global__ __launch_bounds__(128, 2) void k_gemm() {
    extern __shared__ char smem_raw[];
    const uint32_t sraw = smem_u32(smem_raw);
    const uint32_t bufs = (sraw + 1023u) & ~1023u;

    const int tid = threadIdx.x;
    const int lane = tid & 31, wid = tid >> 5;
    const int warp_m = wid >> 1, warp_n = wid & 1;   // 2 x 2
    const int nb = blockIdx.x;   // 0..3  fastest -> A-slab L2 dedup
    const int rb = blockIdx.y;   // 0..63

    // --- loader precompute (per-thread invariants) ---
    const int lrow = tid >> 3;                       // 0..15
    const int lc16 = tid & 7;
    const uint32_t lsw = (uint32_t)(lrow * 128 + ((lc16 * 16) ^ ((lrow & 7) << 4)));
    const __half* pA = g_feat_h + (size_t)(rb * TILE_M + lrow) * FEAT + lc16 * 8;
    const __half* pB = g_w_h   + (size_t)(nb * TILE_N + lrow) * FEAT + lc16 * 8;
    const uint32_t smA = bufs + OFF_A + lsw;
    const uint32_t smB = bufs + OFF_B + lsw;

    auto load_stage = [&](const __half* a, const __half* b, uint32_t bb) {
#pragma unroll
        for (int it = 0; it < 8; ++it)
            cp_async16(smA + bb + (unsigned)it * 2048u, a + (size_t)it * (16 * FEAT));
#pragma unroll
        for (int it = 0; it < 8; ++it)
            cp_async16(smB + bb + (unsigned)it * 2048u, b + (size_t)it * (16 * FEAT));
        cp_commit();
    };

    // --- ldsm per-lane geometry (validated R11-R16) ---
    const int rowA = lane & 15;
    const int khA  = lane >> 4;
    const int rowB = (lane & 7) + 8 * (lane >> 4);
    const int khB  = (lane >> 3) & 1;
    const uint32_t swz = (uint32_t)((lane & 7) << 4);
    const uint32_t cbaseA = OFF_A + (unsigned)((warp_m * 64 + rowA) * 128);
    const uint32_t cbaseB = OFF_B + (unsigned)((warp_n * 64 + rowB) * 128);

    float acc[4][8][4];
#pragma unroll
    for (int i = 0; i < 4; ++i)
#pragma unroll
        for (int j = 0; j < 8; ++j)
#pragma unroll
            for (int q = 0; q < 4; ++q) acc[i][j][q] = 0.f;

    load_stage(pA, pB, 0);          pA += KC; pB += KC;
    load_stage(pA, pB, BUF_STRIDE); pA += KC; pB += KC;

    uint32_t bb_load = 2u * BUF_STRIDE;   // buffer offset for next prefetch
    uint32_t bb_comp = 0u;                // buffer offset being computed

#pragma unroll 1
    for (int s = 0; s < NSTAGE; ++s) {
        if (s < NSTAGE - 1) cp_wait<1>(); else cp_wait<0>();
        __syncthreads();  // stage s visible; all warps done with stage s-1

        const uint32_t baseA = bufs + bb_comp + cbaseA;
        const uint32_t baseB = bufs + bb_comp + cbaseB;

        uint32_t a[2][4][4], b[4][4];
        // preload A fragments for ks=0 right after the barrier
        {
            const uint32_t CA = (uint32_t)(khA * 16) ^ swz;
#pragma unroll
            for (int i = 0; i < 4; ++i)
                ldsm_x4(a[0][i][0], a[0][i][1], a[0][i][2], a[0][i][3],
                        baseA + (unsigned)(i * 2048) + CA);
        }

        if (s + 2 < NSTAGE) {
            load_stage(pA, pB, bb_load);
            pA += KC; pB += KC;
            bb_load += BUF_STRIDE;
            if (bb_load == 3u * BUF_STRIDE) bb_load = 0u;
        }

#pragma unroll
        for (int ks = 0; ks < 4; ++ks) {
            const uint32_t CB = (uint32_t)((ks * 32) | (khB * 16)) ^ swz;
#pragma unroll
            for (int j2 = 0; j2 < 4; ++j2)
                ldsm_x4(b[j2][0], b[j2][1], b[j2][2], b[j2][3],
                        baseB + (unsigned)(j2 * 2048) + CB);
            if (ks < 3) {   // prefetch next ks A fragments
                const uint32_t CA = (uint32_t)(((ks + 1) * 32) | (khA * 16)) ^ swz;
#pragma unroll
                for (int i = 0; i < 4; ++i)
                    ldsm_x4(a[(ks + 1) & 1][i][0], a[(ks + 1) & 1][i][1],
                            a[(ks + 1) & 1][i][2], a[(ks + 1) & 1][i][3],
                            baseA + (unsigned)(i * 2048) + CA);
            }
#pragma unroll
            for (int i = 0; i < 4; ++i)
#pragma unroll
                for (int j2 = 0; j2 < 4; ++j2) {
                    mma16816(acc[i][2 * j2 + 0], a[ks & 1][i], &b[j2][0]);
                    mma16816(acc[i][2 * j2 + 1], a[ks & 1][i], &b[j2][2]);
                }
        }
        bb_comp += BUF_STRIDE;
        if (bb_comp == 3u * BUF_STRIDE) bb_comp = 0u;
    }

    // epilogue: fragments -> g_acc (fp32)
    const int r  = lane >> 2;
    const int cc = 2 * (lane & 3);
    const int m0 = rb * TILE_M + warp_m * 64;
    const int n0 = nb * TILE_N + warp_n * 64;
#pragma unroll
    for (int i = 0; i < 4; ++i)
#pragma unroll
        for (int j = 0; j < 8; ++j) {
            const int m = m0 + i * 16 + r;
            const int n = n0 + j * 8 + cc;
            *reinterpret_cast<float2*>(&g_acc[(size_t)m * MOUT + n]) =
                make_float2(acc[i][j][0], acc[i][j][1]);
            *reinterpret_cast<float2*>(&g_acc[(size_t)(m + 8) * MOUT + n]) =
                make_float2(acc[i][j][2], acc[i][j][3]);
        }
}

// ---------------- kernel 3: bias + corr + stm + clip + MLP head ----------------
__global__ __launch_bounds__(128) void k_mlp(const float* __restrict__ stm,
                                             const float* __restrict__ b_ft,
                                             const float* __restrict__ W1,
                                             const float* __restrict__ b1,
                                             const float* __restrict__ W2,
                                             const float* __restrict__ b2,
                                             float* __restrict__ out) {
    __shared__ float l1[1024];
    __shared__ float l2[32];
    const int b = blockIdx.x, t = threadIdx.x;
    const float s0 = stm[b * 2 + 0], s1 = stm[b * 2 + 1];
#pragma unroll
    for (int it = 0; it < 8; ++it) {
        int i = t + it * 128;
        int p = i >> 9, m = i & 511;
        float v = (g_acc[(size_t)(b * 2 + p) * MOUT + m] + g_corr[m] + b_ft[m]) * (p ? s1 : s0);
        l1[i] = fminf(fmaxf(v, 0.f), 1.f);
    }
    __syncthreads();
    const int w = t >> 5, lane = t & 31;
#pragma unroll 1
    for (int jj = 0; jj < 8; ++jj) {
        int j = w * 8 + jj;
        const float* wr = W1 + (size_t)j * 1024;
        float s = 0.f;
#pragma unroll 8
        for (int i = lane; i < 1024; i += 32) s += l1[i] * wr[i];
#pragma unroll
        for (int o = 16; o; o >>= 1) s += __shfl_xor_sync(0xffffffffu, s, o);
        if (lane == 0) l2[j] = fminf(fmaxf(s + b1[j], 0.f), 1.f);
    }
    __syncthreads();
    if (t < 32) {
        float s = l2[t] * W2[t];
#pragma unroll
        for (int o = 16; o; o >>= 1) s += __shfl_xor_sync(0xffffffffu, s, o);
        if (t == 0) out[b] = s + b2[0];
    }
}

extern "C" void kernel_launch(void* const* d_in, const int* in_sizes, int n_in,
                              void* d_out, int out_size) {
    const float* features = (const float*)d_in[0];
    const float* stm      = (const float*)d_in[1];
    const float* W_ft     = (const float*)d_in[2];
    const float* b_ft     = (const float*)d_in[3];
    const float* W1       = (const float*)d_in[4];
    const float* b1       = (const float*)d_in[5];
    const float* W2       = (const float*)d_in[6];
    const float* b2       = (const float*)d_in[7];
    float* out = (float*)d_out;

    cudaFuncSetAttribute(k_gemm, cudaFuncAttributeMaxDynamicSharedMemorySize, DYN_SMEM);

    k_convert_feat<<<(unsigned)((NF8 + 255) / 256), 256>>>(features);
    k_convert_wc<<<MOUT, 256>>>(W_ft);
    k_gemm<<<dim3(4, 64), 128, DYN_SMEM>>>();
    k_mlp<<<BATCH, 128>>>(stm, b_ft, W1, b1, W2, b2, out);
}